// round 5
// baseline (speedup 1.0000x reference)
#include <cuda_runtime.h>

// Problem constants
#define BB   4
#define HH   56
#define WW   56
#define CC   128
#define NHD  4
#define HD   32
#define KS   7
#define NB   3              // neighborhood radius
#define MTOK (BB*HH*WW)     // 12544
#define QKVN (3*CC)         // 384
#define SCALE 0.17677669529663687f   // 1/sqrt(32)

// Scratch (device globals; no allocation anywhere)
__device__ float g_qkv[MTOK * QKVN];   // [tok][3*C]  s*128 + n*32 + d
__device__ float g_att[MTOK * CC];     // [tok][C]    n*32 + d

// ----------------------------------------------------------------------------
// fp32 GEMM: C[M,N] = A[M,K] @ B[K,N] + bias[N]
// BM=BN=64, BK=16, 256 threads, 4x4 per-thread microtile.
// M % 64 == 0, N % 64 == 0, K % 16 == 0 guaranteed by caller.
// ----------------------------------------------------------------------------
__global__ __launch_bounds__(256) void gemm_bias_kernel(
    const float* __restrict__ A, const float* __restrict__ B,
    const float* __restrict__ bias, float* __restrict__ C,
    int M, int N, int K)
{
    __shared__ float As[16][64];   // [k][m] (transposed store)
    __shared__ float Bs[16][64];   // [k][n]

    const int tid = threadIdx.x;
    const int tm  = tid >> 4;      // 0..15 -> rows tm*4..tm*4+3
    const int tn  = tid & 15;      // 0..15 -> cols tn*4..tn*4+3
    const int rowBase = blockIdx.y * 64;
    const int colBase = blockIdx.x * 64;

    // load-index decomposition
    const int lm  = tid >> 2;          // 0..63 (A row within tile)
    const int lk4 = (tid & 3) * 4;     // 0,4,8,12 (A k within tile)
    const int bk  = tid >> 4;          // 0..15 (B k within tile)
    const int bn4 = (tid & 15) * 4;    // B col within tile

    float acc[4][4];
    #pragma unroll
    for (int i = 0; i < 4; i++)
        #pragma unroll
        for (int j = 0; j < 4; j++) acc[i][j] = 0.f;

    for (int k0 = 0; k0 < K; k0 += 16) {
        float4 a4 = *(const float4*)&A[(rowBase + lm) * K + k0 + lk4];
        As[lk4 + 0][lm] = a4.x;
        As[lk4 + 1][lm] = a4.y;
        As[lk4 + 2][lm] = a4.z;
        As[lk4 + 3][lm] = a4.w;
        *(float4*)&Bs[bk][bn4] = *(const float4*)&B[(k0 + bk) * N + colBase + bn4];
        __syncthreads();

        #pragma unroll
        for (int kk = 0; kk < 16; kk++) {
            float4 av = *(const float4*)&As[kk][tm * 4];
            float4 bv = *(const float4*)&Bs[kk][tn * 4];
            float ar[4] = {av.x, av.y, av.z, av.w};
            float br[4] = {bv.x, bv.y, bv.z, bv.w};
            #pragma unroll
            for (int i = 0; i < 4; i++)
                #pragma unroll
                for (int j = 0; j < 4; j++)
                    acc[i][j] += ar[i] * br[j];
        }
        __syncthreads();
    }

    #pragma unroll
    for (int i = 0; i < 4; i++) {
        float4 o;
        o.x = acc[i][0] + bias[colBase + tn * 4 + 0];
        o.y = acc[i][1] + bias[colBase + tn * 4 + 1];
        o.z = acc[i][2] + bias[colBase + tn * 4 + 2];
        o.w = acc[i][3] + bias[colBase + tn * 4 + 3];
        *(float4*)&C[(rowBase + tm * 4 + i) * N + colBase + tn * 4] = o;
    }
}

// ----------------------------------------------------------------------------
// Neighborhood attention.
// Block = (b, head, 7x7 query tile). Window = 13x13 keys (<=169 positions).
// K/V staged transposed in smem: Ks[d*169 + pos]. One thread per query.
// ----------------------------------------------------------------------------
#define TQ   7
#define WIN  13
#define WPOS 169

__global__ __launch_bounds__(64) void natten_kernel(
    const float* __restrict__ qkv, const float* __restrict__ rpb,
    float* __restrict__ o)
{
    __shared__ float Ks[HD * WPOS];   // 21.6 KB
    __shared__ float Vs[HD * WPOS];   // 21.6 KB
    __shared__ float Bsm[WPOS];       // rpb for this head

    const int tid = threadIdx.x;
    const int bn  = blockIdx.y;
    const int n   = bn & 3;
    const int b   = bn >> 2;
    const int ty  = blockIdx.x >> 3;
    const int tx  = blockIdx.x & 7;
    const int ti0 = ty * TQ;
    const int tj0 = tx * TQ;

    // Key window covered by this tile.
    // Per-query window start si = clip(i - NB, 0, HH - KS); over the tile the
    // union of keys is [min_si, max_si + KS - 1]:
    //   min_si = max(ti0 - NB, 0)          (ti0 <= HH-KS always here)
    //   max_si = min(ti0 + TQ - 1 - NB, HH - KS) ... but tile queries go to
    //   ti0+6, so max_si = min(ti0 + NB, HH - KS)  (TQ-1-NB == NB for K=7)
    const int wi0 = max(ti0 - NB, 0);
    const int wi1 = min(ti0 + NB, HH - KS) + (KS - 1);
    const int wj0 = max(tj0 - NB, 0);
    const int wj1 = min(tj0 + NB, WW - KS) + (KS - 1);
    const int nr = wi1 - wi0 + 1;   // <= 13
    const int nc = wj1 - wj0 + 1;   // <= 13

    // stage rpb for this head
    for (int i = tid; i < WPOS; i += 64) Bsm[i] = rpb[n * WPOS + i];

    // stage K,V transposed: Ks[(4f+e)*169 + r*13+c]
    const int npos = nr * nc;
    for (int idx = tid; idx < npos * 8; idx += 64) {
        int pos = idx >> 3, f = idx & 7;
        int r = pos / nc, c = pos - r * nc;
        int tok = (b * HH + wi0 + r) * WW + (wj0 + c);
        const float* base = qkv + tok * QKVN + n * HD + f * 4;
        float4 kv = *(const float4*)(base + CC);
        float4 vv = *(const float4*)(base + 2 * CC);
        int spos = r * WIN + c;
        Ks[(f * 4 + 0) * WPOS + spos] = kv.x;
        Ks[(f * 4 + 1) * WPOS + spos] = kv.y;
        Ks[(f * 4 + 2) * WPOS + spos] = kv.z;
        Ks[(f * 4 + 3) * WPOS + spos] = kv.w;
        Vs[(f * 4 + 0) * WPOS + spos] = vv.x;
        Vs[(f * 4 + 1) * WPOS + spos] = vv.y;
        Vs[(f * 4 + 2) * WPOS + spos] = vv.z;
        Vs[(f * 4 + 3) * WPOS + spos] = vv.w;
    }
    __syncthreads();

    if (tid >= TQ * TQ) return;

    const int qi = tid / TQ, qj = tid - (tid / TQ) * TQ;
    const int i = ti0 + qi, j = tj0 + qj;
    const int si = min(max(i - NB, 0), HH - KS);
    const int sj = min(max(j - NB, 0), WW - KS);
    const int pbase = (si - wi0) * WIN + (sj - wj0);
    const int bbase = (si - i + 2 * NB) * WIN + (sj - j + 2 * NB);
    const int tok = (b * HH + i) * WW + j;

    // load q (scaled)
    float q[HD];
    {
        const float4* qp = (const float4*)(qkv + tok * QKVN + n * HD);
        #pragma unroll
        for (int f = 0; f < 8; f++) {
            float4 t = qp[f];
            q[4 * f + 0] = t.x * SCALE;
            q[4 * f + 1] = t.y * SCALE;
            q[4 * f + 2] = t.z * SCALE;
            q[4 * f + 3] = t.w * SCALE;
        }
    }

    // scores
    float sc[KS * KS];
    float mx = -1e30f;
    #pragma unroll
    for (int p = 0; p < KS; p++) {
        #pragma unroll
        for (int r = 0; r < KS; r++) {
            const int pos = pbase + p * WIN + r;
            float s = 0.f;
            #pragma unroll
            for (int d = 0; d < HD; d++) s += q[d] * Ks[d * WPOS + pos];
            s += Bsm[bbase + p * WIN + r];
            sc[p * KS + r] = s;
            mx = fmaxf(mx, s);
        }
    }

    // softmax (unnormalized) + AV
    float sum = 0.f;
    #pragma unroll
    for (int t = 0; t < KS * KS; t++) {
        sc[t] = __expf(sc[t] - mx);
        sum += sc[t];
    }
    float acc[HD];
    #pragma unroll
    for (int d = 0; d < HD; d++) acc[d] = 0.f;
    #pragma unroll
    for (int p = 0; p < KS; p++) {
        #pragma unroll
        for (int r = 0; r < KS; r++) {
            const float w = sc[p * KS + r];
            const int pos = pbase + p * WIN + r;
            #pragma unroll
            for (int d = 0; d < HD; d++) acc[d] += w * Vs[d * WPOS + pos];
        }
    }
    const float inv = 1.f / sum;
    float* op = o + tok * CC + n * HD;
    #pragma unroll
    for (int f = 0; f < 8; f++) {
        float4 t;
        t.x = acc[4 * f + 0] * inv;
        t.y = acc[4 * f + 1] * inv;
        t.z = acc[4 * f + 2] * inv;
        t.w = acc[4 * f + 3] * inv;
        *(float4*)(op + 4 * f) = t;
    }
}

// ----------------------------------------------------------------------------
extern "C" void kernel_launch(void* const* d_in, const int* in_sizes, int n_in,
                              void* d_out, int out_size)
{
    const float* x      = (const float*)d_in[0];
    const float* w_qkv  = (const float*)d_in[1];
    const float* b_qkv  = (const float*)d_in[2];
    const float* rpb    = (const float*)d_in[3];
    const float* w_proj = (const float*)d_in[4];
    const float* b_proj = (const float*)d_in[5];
    float* out = (float*)d_out;

    float *qkv, *att;
    cudaGetSymbolAddress((void**)&qkv, g_qkv);
    cudaGetSymbolAddress((void**)&att, g_att);

    // 1) qkv = x @ w_qkv + b_qkv   (M=12544, N=384, K=128)
    dim3 g1(QKVN / 64, MTOK / 64);
    gemm_bias_kernel<<<g1, 256>>>(x, w_qkv, b_qkv, qkv, MTOK, QKVN, CC);

    // 2) neighborhood attention -> att [tok, C]
    dim3 g2(64, BB * NHD);   // 8x8 tiles, b*nh
    natten_kernel<<<g2, 64>>>(qkv, rpb, att);

    // 3) out = att @ w_proj + b_proj  (M=12544, N=128, K=128)
    dim3 g3(CC / 64, MTOK / 64);
    gemm_bias_kernel<<<g3, 256>>>(att, w_proj, b_proj, out, MTOK, CC, CC);
}

// round 6
// speedup vs baseline: 1.0348x; 1.0348x over previous
#include <cuda_runtime.h>

// Problem constants
#define BB   4
#define HH   56
#define WW   56
#define CC   128
#define NHD  4
#define HD   32
#define KS   7
#define NB   3              // neighborhood radius
#define MTOK (BB*HH*WW)     // 12544
#define QKVN (3*CC)         // 384
#define SCALE 0.17677669529663687f   // 1/sqrt(32)

// Scratch (device globals; no allocation anywhere)
__device__ float g_qkv[MTOK * QKVN];   // [tok][3*C]
__device__ float g_att[MTOK * CC];     // [tok][C]

// ----------------------------------------------------------------------------
// fp32 GEMM: C[M,N] = A[M,K] @ B[K,N] + bias[N]
// Templated tile: BM x BN, BK=16, 256 threads, TM x TN per-thread microtile.
// Requires: (BM/TM)*(BN/TN) == 256, M%BM==0, N%BN==0, K%16==0, TN%4==0, TM%4==0.
// ----------------------------------------------------------------------------
template<int BM, int BN, int TM, int TN>
__global__ __launch_bounds__(256) void gemm_bias_kernel(
    const float* __restrict__ A, const float* __restrict__ B,
    const float* __restrict__ bias, float* __restrict__ C,
    int M, int N, int K)
{
    constexpr int BK = 16;
    constexpr int PAD = 4;                 // keeps float4 alignment of rows
    __shared__ float As[BK][BM + PAD];     // [k][m] (transposed store)
    __shared__ float Bs[BK][BN];           // [k][n]

    const int tid = threadIdx.x;
    const int tn  = tid % (BN / TN);
    const int tm  = tid / (BN / TN);
    const int rowBase = blockIdx.y * BM;
    const int colBase = blockIdx.x * BN;

    // A loader: 4 threads per row (float4 along k), 64 rows per pass
    const int lm0 = tid >> 2;              // 0..63
    const int lk4 = (tid & 3) * 4;         // 0,4,8,12
    constexpr int A_PASSES = BM / 64;

    // B loader: BN/4 threads per k-row (one float4 each)
    const int bn4 = (tid % (BN / 4)) * 4;
    const int bk0 = tid / (BN / 4);
    constexpr int B_KROWS_PER_PASS = 256 / (BN / 4);
    constexpr int B_PASSES = BK / B_KROWS_PER_PASS;

    float acc[TM][TN];
    #pragma unroll
    for (int i = 0; i < TM; i++)
        #pragma unroll
        for (int j = 0; j < TN; j++) acc[i][j] = 0.f;

    for (int k0 = 0; k0 < K; k0 += BK) {
        #pragma unroll
        for (int p = 0; p < A_PASSES; p++) {
            const int lm = lm0 + p * 64;
            float4 a4 = *(const float4*)&A[(rowBase + lm) * K + k0 + lk4];
            As[lk4 + 0][lm] = a4.x;
            As[lk4 + 1][lm] = a4.y;
            As[lk4 + 2][lm] = a4.z;
            As[lk4 + 3][lm] = a4.w;
        }
        #pragma unroll
        for (int p = 0; p < B_PASSES; p++) {
            const int bk = bk0 + p * B_KROWS_PER_PASS;
            *(float4*)&Bs[bk][bn4] = *(const float4*)&B[(k0 + bk) * N + colBase + bn4];
        }
        __syncthreads();

        #pragma unroll
        for (int kk = 0; kk < BK; kk++) {
            float ar[TM], br[TN];
            #pragma unroll
            for (int i4 = 0; i4 < TM; i4 += 4) {
                float4 t = *(const float4*)&As[kk][tm * TM + i4];
                ar[i4 + 0] = t.x; ar[i4 + 1] = t.y; ar[i4 + 2] = t.z; ar[i4 + 3] = t.w;
            }
            #pragma unroll
            for (int j4 = 0; j4 < TN; j4 += 4) {
                float4 t = *(const float4*)&Bs[kk][tn * TN + j4];
                br[j4 + 0] = t.x; br[j4 + 1] = t.y; br[j4 + 2] = t.z; br[j4 + 3] = t.w;
            }
            #pragma unroll
            for (int i = 0; i < TM; i++)
                #pragma unroll
                for (int j = 0; j < TN; j++)
                    acc[i][j] += ar[i] * br[j];
        }
        __syncthreads();
    }

    float bv[TN];
    #pragma unroll
    for (int j = 0; j < TN; j++) bv[j] = bias[colBase + tn * TN + j];

    #pragma unroll
    for (int i = 0; i < TM; i++) {
        #pragma unroll
        for (int j4 = 0; j4 < TN; j4 += 4) {
            float4 o;
            o.x = acc[i][j4 + 0] + bv[j4 + 0];
            o.y = acc[i][j4 + 1] + bv[j4 + 1];
            o.z = acc[i][j4 + 2] + bv[j4 + 2];
            o.w = acc[i][j4 + 3] + bv[j4 + 3];
            *(float4*)&C[(rowBase + tm * TM + i) * N + colBase + tn * TN + j4] = o;
        }
    }
}

// ----------------------------------------------------------------------------
// Neighborhood attention (unchanged from passing R5 kernel).
// Block = (b, head, 7x7 query tile). Window = 13x13 keys (<=169 positions).
// ----------------------------------------------------------------------------
#define TQ   7
#define WIN  13
#define WPOS 169

__global__ __launch_bounds__(64) void natten_kernel(
    const float* __restrict__ qkv, const float* __restrict__ rpb,
    float* __restrict__ o)
{
    __shared__ float Ks[HD * WPOS];   // 21.6 KB
    __shared__ float Vs[HD * WPOS];   // 21.6 KB
    __shared__ float Bsm[WPOS];       // rpb for this head

    const int tid = threadIdx.x;
    const int bn  = blockIdx.y;
    const int n   = bn & 3;
    const int b   = bn >> 2;
    const int ty  = blockIdx.x >> 3;
    const int tx  = blockIdx.x & 7;
    const int ti0 = ty * TQ;
    const int tj0 = tx * TQ;

    const int wi0 = max(ti0 - NB, 0);
    const int wi1 = min(ti0 + NB, HH - KS) + (KS - 1);
    const int wj0 = max(tj0 - NB, 0);
    const int wj1 = min(tj0 + NB, WW - KS) + (KS - 1);
    const int nr = wi1 - wi0 + 1;   // <= 13
    const int nc = wj1 - wj0 + 1;   // <= 13

    for (int i = tid; i < WPOS; i += 64) Bsm[i] = rpb[n * WPOS + i];

    const int npos = nr * nc;
    for (int idx = tid; idx < npos * 8; idx += 64) {
        int pos = idx >> 3, f = idx & 7;
        int r = pos / nc, c = pos - r * nc;
        int tok = (b * HH + wi0 + r) * WW + (wj0 + c);
        const float* base = qkv + tok * QKVN + n * HD + f * 4;
        float4 kv = *(const float4*)(base + CC);
        float4 vv = *(const float4*)(base + 2 * CC);
        int spos = r * WIN + c;
        Ks[(f * 4 + 0) * WPOS + spos] = kv.x;
        Ks[(f * 4 + 1) * WPOS + spos] = kv.y;
        Ks[(f * 4 + 2) * WPOS + spos] = kv.z;
        Ks[(f * 4 + 3) * WPOS + spos] = kv.w;
        Vs[(f * 4 + 0) * WPOS + spos] = vv.x;
        Vs[(f * 4 + 1) * WPOS + spos] = vv.y;
        Vs[(f * 4 + 2) * WPOS + spos] = vv.z;
        Vs[(f * 4 + 3) * WPOS + spos] = vv.w;
    }
    __syncthreads();

    if (tid >= TQ * TQ) return;

    const int qi = tid / TQ, qj = tid - (tid / TQ) * TQ;
    const int i = ti0 + qi, j = tj0 + qj;
    const int si = min(max(i - NB, 0), HH - KS);
    const int sj = min(max(j - NB, 0), WW - KS);
    const int pbase = (si - wi0) * WIN + (sj - wj0);
    const int bbase = (si - i + 2 * NB) * WIN + (sj - j + 2 * NB);
    const int tok = (b * HH + i) * WW + j;

    float q[HD];
    {
        const float4* qp = (const float4*)(qkv + tok * QKVN + n * HD);
        #pragma unroll
        for (int f = 0; f < 8; f++) {
            float4 t = qp[f];
            q[4 * f + 0] = t.x * SCALE;
            q[4 * f + 1] = t.y * SCALE;
            q[4 * f + 2] = t.z * SCALE;
            q[4 * f + 3] = t.w * SCALE;
        }
    }

    float sc[KS * KS];
    float mx = -1e30f;
    #pragma unroll
    for (int p = 0; p < KS; p++) {
        #pragma unroll
        for (int r = 0; r < KS; r++) {
            const int pos = pbase + p * WIN + r;
            float s = 0.f;
            #pragma unroll
            for (int d = 0; d < HD; d++) s += q[d] * Ks[d * WPOS + pos];
            s += Bsm[bbase + p * WIN + r];
            sc[p * KS + r] = s;
            mx = fmaxf(mx, s);
        }
    }

    float sum = 0.f;
    #pragma unroll
    for (int t = 0; t < KS * KS; t++) {
        sc[t] = __expf(sc[t] - mx);
        sum += sc[t];
    }
    float acc[HD];
    #pragma unroll
    for (int d = 0; d < HD; d++) acc[d] = 0.f;
    #pragma unroll
    for (int p = 0; p < KS; p++) {
        #pragma unroll
        for (int r = 0; r < KS; r++) {
            const float w = sc[p * KS + r];
            const int pos = pbase + p * WIN + r;
            #pragma unroll
            for (int d = 0; d < HD; d++) acc[d] += w * Vs[d * WPOS + pos];
        }
    }
    const float inv = 1.f / sum;
    float* op = o + tok * CC + n * HD;
    #pragma unroll
    for (int f = 0; f < 8; f++) {
        float4 t;
        t.x = acc[4 * f + 0] * inv;
        t.y = acc[4 * f + 1] * inv;
        t.z = acc[4 * f + 2] * inv;
        t.w = acc[4 * f + 3] * inv;
        *(float4*)(op + 4 * f) = t;
    }
}

// ----------------------------------------------------------------------------
extern "C" void kernel_launch(void* const* d_in, const int* in_sizes, int n_in,
                              void* d_out, int out_size)
{
    const float* x      = (const float*)d_in[0];
    const float* w_qkv  = (const float*)d_in[1];
    const float* b_qkv  = (const float*)d_in[2];
    const float* rpb    = (const float*)d_in[3];
    const float* w_proj = (const float*)d_in[4];
    const float* b_proj = (const float*)d_in[5];
    float* out = (float*)d_out;

    float *qkv, *att;
    cudaGetSymbolAddress((void**)&qkv, g_qkv);
    cudaGetSymbolAddress((void**)&att, g_att);

    // 1) qkv = x @ w_qkv + b_qkv   (M=12544, N=384, K=128)  -> 98 x 3 CTAs
    dim3 g1(QKVN / 128, MTOK / 128);
    gemm_bias_kernel<128, 128, 8, 8><<<g1, 256>>>(x, w_qkv, b_qkv, qkv, MTOK, QKVN, CC);

    // 2) neighborhood attention -> att [tok, C]
    dim3 g2(64, BB * NHD);   // 8x8 tiles, b*nh
    natten_kernel<<<g2, 64>>>(qkv, rpb, att);

    // 3) out = att @ w_proj + b_proj  (M=12544, N=128, K=128) -> 98 x 2 CTAs
    dim3 g3(CC / 64, MTOK / 128);
    gemm_bias_kernel<128, 64, 8, 4><<<g3, 256>>>(att, w_proj, b_proj, out, MTOK, CC, CC);
}